// round 16
// baseline (speedup 1.0000x reference)
#include <cuda_runtime.h>
#include <cuda_fp16.h>
#include <cuda_bf16.h>

#define N_NODES 100000
#define N_EDGES 3200000
#define N_GRAPHS 256
// DIMS: 38 -> 64 -> 32 -> 16

// ---------------- scratch (static device globals; no allocs) ----------------
__device__ float  g_x40 [N_NODES * 40];
__device__ __half g_x40h[N_NODES * 40];   // fp16 gather payload (layer 0)
__device__ float  g_agg0[N_NODES * 40];
__device__ float  g_agg1[N_NODES * 32];
__device__ float  g_agg2[N_NODES * 16];
__device__ float  g_h1[N_NODES * 64];
__device__ __half g_y1h[N_NODES * 32];    // fp16 gather payload (layer 1)
__device__ __half g_y2h[N_NODES * 16];    // fp16 gather payload (layer 2)
__device__ float  g_z2[N_NODES * 16];
__device__ int    g_src[N_EDGES];
__device__ int    g_dst[N_EDGES];
__device__ int    g_ssrc[N_EDGES];        // src sorted by dst (CSR payload)
__device__ int    g_rowptr[N_NODES + 1];
__device__ int    g_cursor[N_NODES];
__device__ int    g_blocksum[512];
__device__ float  g_pool[N_GRAPHS * 16];
__device__ float  g_cnt[N_GRAPHS];
__device__ int    g_ei_is64;
__device__ int    g_b_is64;

// ---------------- dtype detection (int32 vs int64 buffers) ------------------
__global__ void k_detect(const int* __restrict__ ei_raw,
                         const int* __restrict__ b_raw) {
    int nz = 0;
    #pragma unroll
    for (int i = 0; i < 64; i++) nz |= ei_raw[2 * i + 1];
    g_ei_is64 = (nz == 0) ? 1 : 0;
    g_b_is64 = (b_raw[N_NODES - 1] == 0) ? 1 : 0;
}

// ---------------- prep: convert indices, pack x (fp32+fp16), zero -----------
__global__ void k_prep(const float* __restrict__ x,
                       const int* __restrict__ ei_raw) {
    long long i = (long long)blockIdx.x * blockDim.x + threadIdx.x;
    long long stride = (long long)gridDim.x * blockDim.x;
    int is64 = g_ei_is64;
    for (long long e = i; e < N_EDGES; e += stride) {
        if (is64) {
            g_src[e] = ei_raw[2 * e];
            g_dst[e] = ei_raw[2 * ((long long)N_EDGES + e)];
        } else {
            g_src[e] = ei_raw[e];
            g_dst[e] = ei_raw[N_EDGES + e];
        }
    }
    for (long long k = i; k < (long long)N_NODES * 40; k += stride) {
        int j = (int)(k % 40);
        float v = (j < 38) ? x[(k / 40) * 38 + j] : 0.f;
        g_x40[k] = v;
        g_x40h[k] = __float2half(v);
    }
    for (long long k = i; k < N_NODES; k += stride) g_cursor[k] = 0;
    for (long long k = i; k < N_GRAPHS * 16; k += stride) g_pool[k] = 0.f;
    for (long long k = i; k < N_GRAPHS; k += stride) g_cnt[k] = 0.f;
}

// ---------------- CSR build: histogram -> scan -> place ---------------------
__global__ void k_hist() {
    int i = blockIdx.x * blockDim.x + threadIdx.x;
    int stride = gridDim.x * blockDim.x;
    for (int e = i; e < N_EDGES; e += stride)
        atomicAdd(&g_cursor[g_dst[e]], 1);
}

__global__ void k_scan1() {
    __shared__ int sh[256];
    int i = blockIdx.x * 256 + threadIdx.x;
    int v = (i < N_NODES) ? g_cursor[i] : 0;
    sh[threadIdx.x] = v;
    __syncthreads();
    for (int off = 1; off < 256; off <<= 1) {
        int t = (threadIdx.x >= off) ? sh[threadIdx.x - off] : 0;
        __syncthreads();
        sh[threadIdx.x] += t;
        __syncthreads();
    }
    if (i < N_NODES) g_rowptr[i] = sh[threadIdx.x] - v;
    if (threadIdx.x == 255) g_blocksum[blockIdx.x] = sh[255];
}

__global__ void k_scan2() {
    __shared__ int sh[512];
    int v = (threadIdx.x < 391) ? g_blocksum[threadIdx.x] : 0;
    sh[threadIdx.x] = v;
    __syncthreads();
    for (int off = 1; off < 512; off <<= 1) {
        int t = (threadIdx.x >= off) ? sh[threadIdx.x - off] : 0;
        __syncthreads();
        sh[threadIdx.x] += t;
        __syncthreads();
    }
    if (threadIdx.x < 391) g_blocksum[threadIdx.x] = sh[threadIdx.x] - v;
}

__global__ void k_scan3() {
    int i = blockIdx.x * 256 + threadIdx.x;
    if (i < N_NODES) {
        int r = g_rowptr[i] + g_blocksum[blockIdx.x];
        g_rowptr[i] = r;
        g_cursor[i] = r;
    }
    if (i == 0) g_rowptr[N_NODES] = N_EDGES;
}

__global__ void k_place() {
    int i = blockIdx.x * blockDim.x + threadIdx.x;
    int stride = gridDim.x * blockDim.x;
    for (int e = i; e < N_EDGES; e += stride) {
        int d = g_dst[e];
        int p = atomicAdd(&g_cursor[d], 1);
        g_ssrc[p] = g_src[e];
    }
}

// ---------------- CSR gather-sum: warp-per-node, fp16 payload, MLP=8 --------
__global__ void k_agg0() {
    int w = (blockIdx.x * blockDim.x + threadIdx.x) >> 5;
    int lane = threadIdx.x & 31;
    if (w >= N_NODES) return;
    int beg = g_rowptr[w], end = g_rowptr[w + 1];
    float a = 0.f, b = 0.f;
    int k = beg;
    for (; k + 8 <= end; k += 8) {
        int s[8];
        #pragma unroll
        for (int j = 0; j < 8; j++) s[j] = g_ssrc[k + j];
        float v[8];
        #pragma unroll
        for (int j = 0; j < 8; j++) v[j] = __half2float(g_x40h[s[j] * 40 + lane]);
        a += ((v[0]+v[1]) + (v[2]+v[3])) + ((v[4]+v[5]) + (v[6]+v[7]));
        if (lane < 8) {
            float u[8];
            #pragma unroll
            for (int j = 0; j < 8; j++) u[j] = __half2float(g_x40h[s[j] * 40 + 32 + lane]);
            b += ((u[0]+u[1]) + (u[2]+u[3])) + ((u[4]+u[5]) + (u[6]+u[7]));
        }
    }
    for (; k < end; k++) {
        int s = g_ssrc[k];
        a += __half2float(g_x40h[s * 40 + lane]);
        if (lane < 8) b += __half2float(g_x40h[s * 40 + 32 + lane]);
    }
    g_agg0[w * 40 + lane] = a;
    if (lane < 8) g_agg0[w * 40 + 32 + lane] = b;
}

__global__ void k_agg1() {
    int w = (blockIdx.x * blockDim.x + threadIdx.x) >> 5;
    int lane = threadIdx.x & 31;
    if (w >= N_NODES) return;
    int beg = g_rowptr[w], end = g_rowptr[w + 1];
    float a = 0.f;
    int k = beg;
    for (; k + 8 <= end; k += 8) {
        int s[8];
        #pragma unroll
        for (int j = 0; j < 8; j++) s[j] = g_ssrc[k + j];
        float v[8];
        #pragma unroll
        for (int j = 0; j < 8; j++) v[j] = __half2float(g_y1h[s[j] * 32 + lane]);
        a += ((v[0]+v[1]) + (v[2]+v[3])) + ((v[4]+v[5]) + (v[6]+v[7]));
    }
    for (; k < end; k++)
        a += __half2float(g_y1h[g_ssrc[k] * 32 + lane]);
    g_agg1[w * 32 + lane] = a;
}

__global__ void k_agg2() {
    int tid = blockIdx.x * blockDim.x + threadIdx.x;
    int n = tid >> 4;
    int f = tid & 15;
    if (n >= N_NODES) return;
    int beg = g_rowptr[n], end = g_rowptr[n + 1];
    float a = 0.f;
    int k = beg;
    for (; k + 8 <= end; k += 8) {
        int s[8];
        #pragma unroll
        for (int j = 0; j < 8; j++) s[j] = g_ssrc[k + j];
        float v[8];
        #pragma unroll
        for (int j = 0; j < 8; j++) v[j] = __half2float(g_y2h[s[j] * 16 + f]);
        a += ((v[0]+v[1]) + (v[2]+v[3])) + ((v[4]+v[5]) + (v[6]+v[7]));
    }
    for (; k < end; k++)
        a += __half2float(g_y2h[g_ssrc[k] * 16 + f]);
    g_agg2[n * 16 + f] = a;
}

// ---------------- node kernel 0: 16 nodes/iter, ILP=4, 2 blocks/SM ----------
__global__ void __launch_bounds__(256, 2)
k_node0(const float* __restrict__ Wr0,  // [64,38]
        const float* __restrict__ b0,   // [64]
        const float* __restrict__ Wt0,  // [64,38]
        const float* __restrict__ Wr1)  // [32,64]
{
    int t = threadIdx.x;
    int o = t & 63, sl = t >> 6;
    float wr[40], wt[40];
    #pragma unroll
    for (int j = 0; j < 40; j++) {
        wr[j] = (j < 38) ? Wr0[o * 38 + j] : 0.f;
        wt[j] = (j < 38) ? Wt0[o * 38 + j] : 0.f;
    }
    float bias = b0[o];
    int oo = o & 31, jb = (o < 32) ? 0 : 32;

    __shared__ float  sW1[32 * 65];
    __shared__ float4 sa4[16][10], sx4[16][10];
    __shared__ float  sh[16][64];
    __shared__ float  sp[16][64];
    for (int i = t; i < 32 * 64; i += 256) sW1[(i >> 6) * 65 + (i & 63)] = Wr1[i];
    __syncthreads();

    for (int nbase = blockIdx.x * 16; nbase < N_NODES; nbase += gridDim.x * 16) {
        for (int i = t; i < 320; i += 256) {
            int n2 = i / 20, r = i % 20;
            int nn = nbase + n2;
            if (nn < N_NODES) {
                if (r < 10) sa4[n2][r] = *(const float4*)&g_agg0[nn * 40 + r * 4];
                else        sx4[n2][r - 10] = *(const float4*)&g_x40[nn * 40 + (r - 10) * 4];
            }
        }
        __syncthreads();
        float h0 = bias, h1v = bias, h2v = bias, h3 = bias;
        #pragma unroll
        for (int c = 0; c < 10; c++) {
            float w0 = wr[4*c+0], w1_ = wr[4*c+1], w2_ = wr[4*c+2], w3 = wr[4*c+3];
            float u0 = wt[4*c+0], u1 = wt[4*c+1], u2 = wt[4*c+2], u3 = wt[4*c+3];
            float4 a, xv;
            a = sa4[sl][c];      xv = sx4[sl][c];
            h0 += w0*a.x + w1_*a.y + w2_*a.z + w3*a.w + u0*xv.x + u1*xv.y + u2*xv.z + u3*xv.w;
            a = sa4[sl+4][c];    xv = sx4[sl+4][c];
            h1v += w0*a.x + w1_*a.y + w2_*a.z + w3*a.w + u0*xv.x + u1*xv.y + u2*xv.z + u3*xv.w;
            a = sa4[sl+8][c];    xv = sx4[sl+8][c];
            h2v += w0*a.x + w1_*a.y + w2_*a.z + w3*a.w + u0*xv.x + u1*xv.y + u2*xv.z + u3*xv.w;
            a = sa4[sl+12][c];   xv = sx4[sl+12][c];
            h3 += w0*a.x + w1_*a.y + w2_*a.z + w3*a.w + u0*xv.x + u1*xv.y + u2*xv.z + u3*xv.w;
        }
        h0 = tanhf(h0); h1v = tanhf(h1v); h2v = tanhf(h2v); h3 = tanhf(h3);
        float hq[4] = {h0, h1v, h2v, h3};
        #pragma unroll
        for (int q = 0; q < 4; q++) {
            int nl = sl + 4 * q, node = nbase + nl;
            if (node < N_NODES) g_h1[node * 64 + o] = hq[q];
            sh[nl][o] = hq[q];
        }
        __syncthreads();
        #pragma unroll
        for (int q = 0; q < 4; q++) {
            int nl = sl + 4 * q;
            float p = 0.f;
            #pragma unroll
            for (int c = 0; c < 8; c++) {
                float4 hv = *(const float4*)&sh[nl][jb + c * 4];
                const float* wrow = &sW1[oo * 65 + jb + c * 4];
                p += wrow[0]*hv.x + wrow[1]*hv.y + wrow[2]*hv.z + wrow[3]*hv.w;
            }
            sp[nl][o] = p;
        }
        __syncthreads();
        if (o < 32) {
            #pragma unroll
            for (int q = 0; q < 4; q++) {
                int nl = sl + 4 * q, node = nbase + nl;
                if (node < N_NODES)
                    g_y1h[node * 32 + o] = __float2half(sp[nl][o] + sp[nl][o + 32]);
            }
        }
        __syncthreads();
    }
}

// ---------------- node kernel 1: h2 -> y2 (half) AND z2 (fp32) --------------
__global__ void __launch_bounds__(256, 2)
k_node1(const float* __restrict__ b1,   // [32]
        const float* __restrict__ Wt1,  // [32,64]
        const float* __restrict__ Wr2,  // [16,32]
        const float* __restrict__ Wt2)  // [16,32]
{
    int t = threadIdx.x;
    int o = t & 31, sl = t >> 5;
    float wt1[64];
    #pragma unroll
    for (int j = 0; j < 64; j++) wt1[j] = Wt1[o * 64 + j];
    float bias = b1[o];
    int oo = o & 15, jb = (o < 16) ? 0 : 16;

    __shared__ float sW2y[16 * 33];
    __shared__ float sW2z[16 * 33];
    __shared__ float sh1[32][64];
    __shared__ float sh2[32][32];
    for (int i = t; i < 16 * 32; i += 256) {
        sW2y[(i >> 5) * 33 + (i & 31)] = Wr2[i];
        sW2z[(i >> 5) * 33 + (i & 31)] = Wt2[i];
    }
    __syncthreads();

    for (int nbase = blockIdx.x * 32; nbase < N_NODES; nbase += gridDim.x * 32) {
        for (int i = t; i < 512; i += 256) {
            int n2 = i >> 4, r = i & 15;
            int nn = nbase + n2;
            if (nn < N_NODES)
                *(float4*)&sh1[n2][r * 4] = *(const float4*)&g_h1[nn * 64 + r * 4];
        }
        __syncthreads();
        float hq[4];
        #pragma unroll
        for (int q = 0; q < 4; q++) {
            int nl = sl + 8 * q, node = nbase + nl;
            float h = bias;
            if (node < N_NODES) h += g_agg1[node * 32 + o];
            #pragma unroll
            for (int c = 0; c < 16; c++) {
                float4 hv = *(const float4*)&sh1[nl][c * 4];
                h += wt1[4*c+0]*hv.x + wt1[4*c+1]*hv.y + wt1[4*c+2]*hv.z + wt1[4*c+3]*hv.w;
            }
            hq[q] = tanhf(h);
        }
        #pragma unroll
        for (int q = 0; q < 4; q++) sh2[sl + 8 * q][o] = hq[q];
        __syncwarp();
        #pragma unroll
        for (int q = 0; q < 4; q++) {
            int nl = sl + 8 * q, node = nbase + nl;
            float py = 0.f, pz = 0.f;
            #pragma unroll
            for (int c = 0; c < 4; c++) {
                float4 hv = *(const float4*)&sh2[nl][jb + c * 4];
                const float* wy = &sW2y[oo * 33 + jb + c * 4];
                const float* wz = &sW2z[oo * 33 + jb + c * 4];
                py += wy[0]*hv.x + wy[1]*hv.y + wy[2]*hv.z + wy[3]*hv.w;
                pz += wz[0]*hv.x + wz[1]*hv.y + wz[2]*hv.z + wz[3]*hv.w;
            }
            float oy = __shfl_down_sync(0xffffffffu, py, 16);
            float oz = __shfl_down_sync(0xffffffffu, pz, 16);
            if (node < N_NODES && o < 16) {
                g_y2h[node * 16 + o] = __float2half(py + oy);
                g_z2[node * 16 + o] = pz + oz;
            }
        }
        __syncthreads();
    }
}

// ---------------- node kernel 2 + pooling: pure elementwise -----------------
__global__ void k_node2_pool(const int* __restrict__ batch_raw,
                             const float* __restrict__ b2)   // [16]
{
    int idx = blockIdx.x * blockDim.x + threadIdx.x;
    if (idx >= N_NODES * 16) return;
    int node = idx >> 4, o = idx & 15;
    float acc = g_agg2[idx] + g_z2[idx] + __ldg(&b2[o]);
    int g = g_b_is64 ? batch_raw[2 * node] : batch_raw[node];
    atomicAdd(&g_pool[g * 16 + o], acc);
    if (o == 0) atomicAdd(&g_cnt[g], 1.0f);
}

// ---------------- final: out = tanh(pool / max(cnt,1)) ----------------------
__global__ void k_final(float* __restrict__ out) {
    int t = blockIdx.x * blockDim.x + threadIdx.x;
    if (t < N_GRAPHS * 16) {
        int g = t >> 4;
        out[t] = tanhf(g_pool[t] / fmaxf(g_cnt[g], 1.0f));
    }
}

extern "C" void kernel_launch(void* const* d_in, const int* in_sizes, int n_in,
                              void* d_out, int out_size) {
    const float* x         = (const float*)d_in[0];
    const int*   ei_raw    = (const int*)d_in[1];
    const int*   batch_raw = (const int*)d_in[2];
    const float* Wr0 = (const float*)d_in[3];
    const float* b0  = (const float*)d_in[4];
    const float* Wt0 = (const float*)d_in[5];
    const float* Wr1 = (const float*)d_in[6];
    const float* b1  = (const float*)d_in[7];
    const float* Wt1 = (const float*)d_in[8];
    const float* Wr2 = (const float*)d_in[9];
    const float* b2  = (const float*)d_in[10];
    const float* Wt2 = (const float*)d_in[11];
    float* out = (float*)d_out;

    k_detect<<<1, 1>>>(ei_raw, batch_raw);
    k_prep<<<2048, 256>>>(x, ei_raw);
    // CSR build (once, reused by all 3 layers)
    k_hist<<<2048, 256>>>();
    k_scan1<<<391, 256>>>();
    k_scan2<<<1, 512>>>();
    k_scan3<<<391, 256>>>();
    k_place<<<2048, 256>>>();
    // layer 0
    k_agg0<<<(N_NODES * 32 + 255) / 256, 256>>>();
    k_node0<<<592, 256>>>(Wr0, b0, Wt0, Wr1);
    // layer 1
    k_agg1<<<(N_NODES * 32 + 255) / 256, 256>>>();
    k_node1<<<592, 256>>>(b1, Wt1, Wr2, Wt2);
    // layer 2
    k_agg2<<<(N_NODES * 16 + 255) / 256, 256>>>();
    k_node2_pool<<<(N_NODES * 16 + 255) / 256, 256>>>(batch_raw, b2);
    k_final<<<16, 256>>>(out);
}

// round 17
// speedup vs baseline: 1.0484x; 1.0484x over previous
#include <cuda_runtime.h>
#include <cuda_bf16.h>

#define N_NODES 100000
#define N_EDGES 3200000
#define N_GRAPHS 256
// DIMS: 38 -> 64 -> 32 -> 16

// ---------------- scratch (static device globals; no allocs) ----------------
__device__ float g_x40 [N_NODES * 40];
__device__ float g_agg0[N_NODES * 40];
__device__ float g_agg1[N_NODES * 32];
__device__ float g_h1[N_NODES * 64];
__device__ float g_y1[N_NODES * 32];
__device__ float g_y2[N_NODES * 16];
__device__ float g_z2[N_NODES * 16];
__device__ int   g_src[N_EDGES];
__device__ int   g_dst[N_EDGES];
__device__ int   g_ssrc[N_EDGES];        // src sorted by dst (CSR payload)
__device__ int   g_rowptr[N_NODES + 1];
__device__ int   g_cursor[N_NODES];
__device__ int   g_blocksum[512];
__device__ float g_pool[N_GRAPHS * 16];
__device__ float g_cnt[N_GRAPHS];
__device__ int   g_ei_is64;
__device__ int   g_b_is64;

// ---------------- dtype detection (int32 vs int64 buffers) ------------------
__global__ void k_detect(const int* __restrict__ ei_raw,
                         const int* __restrict__ b_raw) {
    int nz = 0;
    #pragma unroll
    for (int i = 0; i < 64; i++) nz |= ei_raw[2 * i + 1];
    g_ei_is64 = (nz == 0) ? 1 : 0;
    g_b_is64 = (b_raw[N_NODES - 1] == 0) ? 1 : 0;
}

// ---------------- prep: convert indices, pack x, zero small bufs ------------
__global__ void k_prep(const float* __restrict__ x,
                       const int* __restrict__ ei_raw) {
    long long i = (long long)blockIdx.x * blockDim.x + threadIdx.x;
    long long stride = (long long)gridDim.x * blockDim.x;
    int is64 = g_ei_is64;
    for (long long e = i; e < N_EDGES; e += stride) {
        if (is64) {
            g_src[e] = ei_raw[2 * e];
            g_dst[e] = ei_raw[2 * ((long long)N_EDGES + e)];
        } else {
            g_src[e] = ei_raw[e];
            g_dst[e] = ei_raw[N_EDGES + e];
        }
    }
    for (long long k = i; k < (long long)N_NODES * 40; k += stride) {
        int j = (int)(k % 40);
        g_x40[k] = (j < 38) ? x[(k / 40) * 38 + j] : 0.f;
    }
    for (long long k = i; k < N_NODES; k += stride) g_cursor[k] = 0;
    for (long long k = i; k < N_GRAPHS * 16; k += stride) g_pool[k] = 0.f;
    for (long long k = i; k < N_GRAPHS; k += stride) g_cnt[k] = 0.f;
}

// ---------------- CSR build: histogram -> scan -> place ---------------------
__global__ void k_hist() {
    int i = blockIdx.x * blockDim.x + threadIdx.x;
    int stride = gridDim.x * blockDim.x;
    for (int e = i; e < N_EDGES; e += stride)
        atomicAdd(&g_cursor[g_dst[e]], 1);
}

__global__ void k_scan1() {
    __shared__ int sh[256];
    int i = blockIdx.x * 256 + threadIdx.x;
    int v = (i < N_NODES) ? g_cursor[i] : 0;
    sh[threadIdx.x] = v;
    __syncthreads();
    for (int off = 1; off < 256; off <<= 1) {
        int t = (threadIdx.x >= off) ? sh[threadIdx.x - off] : 0;
        __syncthreads();
        sh[threadIdx.x] += t;
        __syncthreads();
    }
    if (i < N_NODES) g_rowptr[i] = sh[threadIdx.x] - v;
    if (threadIdx.x == 255) g_blocksum[blockIdx.x] = sh[255];
}

__global__ void k_scan2() {
    __shared__ int sh[512];
    int v = (threadIdx.x < 391) ? g_blocksum[threadIdx.x] : 0;
    sh[threadIdx.x] = v;
    __syncthreads();
    for (int off = 1; off < 512; off <<= 1) {
        int t = (threadIdx.x >= off) ? sh[threadIdx.x - off] : 0;
        __syncthreads();
        sh[threadIdx.x] += t;
        __syncthreads();
    }
    if (threadIdx.x < 391) g_blocksum[threadIdx.x] = sh[threadIdx.x] - v;
}

__global__ void k_scan3() {
    int i = blockIdx.x * 256 + threadIdx.x;
    if (i < N_NODES) {
        int r = g_rowptr[i] + g_blocksum[blockIdx.x];
        g_rowptr[i] = r;
        g_cursor[i] = r;
    }
    if (i == 0) g_rowptr[N_NODES] = N_EDGES;
}

__global__ void k_place() {
    int i = blockIdx.x * blockDim.x + threadIdx.x;
    int stride = gridDim.x * blockDim.x;
    for (int e = i; e < N_EDGES; e += stride) {
        int d = g_dst[e];
        int p = atomicAdd(&g_cursor[d], 1);
        g_ssrc[p] = g_src[e];
    }
}

// ---------------- CSR gather-sum: warp-per-node, lane = feature, MLP=8 ------
__global__ void k_agg0() {
    int w = (blockIdx.x * blockDim.x + threadIdx.x) >> 5;
    int lane = threadIdx.x & 31;
    if (w >= N_NODES) return;
    int beg = g_rowptr[w], end = g_rowptr[w + 1];
    float a = 0.f, b = 0.f;
    int k = beg;
    for (; k + 8 <= end; k += 8) {
        int s[8];
        #pragma unroll
        for (int j = 0; j < 8; j++) s[j] = g_ssrc[k + j];
        float v[8];
        #pragma unroll
        for (int j = 0; j < 8; j++) v[j] = g_x40[s[j] * 40 + lane];
        a += ((v[0]+v[1]) + (v[2]+v[3])) + ((v[4]+v[5]) + (v[6]+v[7]));
        if (lane < 8) {
            float u[8];
            #pragma unroll
            for (int j = 0; j < 8; j++) u[j] = g_x40[s[j] * 40 + 32 + lane];
            b += ((u[0]+u[1]) + (u[2]+u[3])) + ((u[4]+u[5]) + (u[6]+u[7]));
        }
    }
    for (; k < end; k++) {
        int s = g_ssrc[k];
        a += g_x40[s * 40 + lane];
        if (lane < 8) b += g_x40[s * 40 + 32 + lane];
    }
    g_agg0[w * 40 + lane] = a;
    if (lane < 8) g_agg0[w * 40 + 32 + lane] = b;
}

__global__ void k_agg1() {
    int w = (blockIdx.x * blockDim.x + threadIdx.x) >> 5;
    int lane = threadIdx.x & 31;
    if (w >= N_NODES) return;
    int beg = g_rowptr[w], end = g_rowptr[w + 1];
    float a = 0.f;
    int k = beg;
    for (; k + 8 <= end; k += 8) {
        int s[8];
        #pragma unroll
        for (int j = 0; j < 8; j++) s[j] = g_ssrc[k + j];
        float v[8];
        #pragma unroll
        for (int j = 0; j < 8; j++) v[j] = g_y1[s[j] * 32 + lane];
        a += ((v[0]+v[1]) + (v[2]+v[3])) + ((v[4]+v[5]) + (v[6]+v[7]));
    }
    for (; k < end; k++)
        a += g_y1[g_ssrc[k] * 32 + lane];
    g_agg1[w * 32 + lane] = a;
}

// agg2 FUSED with node2+pool: half-warp-per-node gather, then elementwise
// add of z2+b2 and pool atomics. Deletes the g_agg2 round-trip entirely.
__global__ void k_agg2_pool(const int* __restrict__ batch_raw,
                            const float* __restrict__ b2)   // [16]
{
    int tid = blockIdx.x * blockDim.x + threadIdx.x;
    int n = tid >> 4;
    int f = tid & 15;
    if (n >= N_NODES) return;
    int beg = g_rowptr[n], end = g_rowptr[n + 1];
    float a = 0.f;
    int k = beg;
    for (; k + 8 <= end; k += 8) {
        int s[8];
        #pragma unroll
        for (int j = 0; j < 8; j++) s[j] = g_ssrc[k + j];
        float v[8];
        #pragma unroll
        for (int j = 0; j < 8; j++) v[j] = g_y2[s[j] * 16 + f];
        a += ((v[0]+v[1]) + (v[2]+v[3])) + ((v[4]+v[5]) + (v[6]+v[7]));
    }
    for (; k < end; k++)
        a += g_y2[g_ssrc[k] * 16 + f];
    a += g_z2[n * 16 + f] + __ldg(&b2[f]);
    int g = g_b_is64 ? batch_raw[2 * n] : batch_raw[n];
    atomicAdd(&g_pool[g * 16 + f], a);
    if (f == 0) atomicAdd(&g_cnt[g], 1.0f);
}

// ---------------- node kernel 0: 32 nodes/iter, ILP=8, 2 blocks/SM ----------
// thread: o = t&63 (output), sl = t>>6 (4 slots); node nl = sl + 4q, q<8.
__global__ void __launch_bounds__(256, 2)
k_node0(const float* __restrict__ Wr0,  // [64,38]
        const float* __restrict__ b0,   // [64]
        const float* __restrict__ Wt0,  // [64,38]
        const float* __restrict__ Wr1)  // [32,64]
{
    int t = threadIdx.x;
    int o = t & 63, sl = t >> 6;
    float wr[40], wt[40];
    #pragma unroll
    for (int j = 0; j < 40; j++) {
        wr[j] = (j < 38) ? Wr0[o * 38 + j] : 0.f;
        wt[j] = (j < 38) ? Wt0[o * 38 + j] : 0.f;
    }
    float bias = b0[o];
    int oo = o & 31, jb = (o < 32) ? 0 : 32;

    __shared__ float  sW1[32 * 65];          // Wr1 [32x64] row stride 65
    __shared__ float4 sa4[32][10], sx4[32][10];
    __shared__ float  sh[32][64];
    __shared__ float  sp[32][64];
    for (int i = t; i < 32 * 64; i += 256) sW1[(i >> 6) * 65 + (i & 63)] = Wr1[i];
    __syncthreads();

    for (int nbase = blockIdx.x * 32; nbase < N_NODES; nbase += gridDim.x * 32) {
        for (int i = t; i < 640; i += 256) {
            int n2 = i / 20, r = i % 20;
            int nn = nbase + n2;
            if (nn < N_NODES) {
                if (r < 10) sa4[n2][r] = *(const float4*)&g_agg0[nn * 40 + r * 4];
                else        sx4[n2][r - 10] = *(const float4*)&g_x40[nn * 40 + (r - 10) * 4];
            }
        }
        __syncthreads();
        float h[8];
        #pragma unroll
        for (int q = 0; q < 8; q++) h[q] = bias;
        #pragma unroll
        for (int c = 0; c < 10; c++) {
            float w0 = wr[4*c+0], w1_ = wr[4*c+1], w2_ = wr[4*c+2], w3 = wr[4*c+3];
            float u0 = wt[4*c+0], u1 = wt[4*c+1], u2 = wt[4*c+2], u3 = wt[4*c+3];
            #pragma unroll
            for (int q = 0; q < 8; q++) {
                float4 a = sa4[sl + 4*q][c];
                float4 xv = sx4[sl + 4*q][c];
                h[q] += w0*a.x + w1_*a.y + w2_*a.z + w3*a.w
                      + u0*xv.x + u1*xv.y + u2*xv.z + u3*xv.w;
            }
        }
        #pragma unroll
        for (int q = 0; q < 8; q++) {
            float hv = tanhf(h[q]);
            int nl = sl + 4 * q, node = nbase + nl;
            if (node < N_NODES) g_h1[node * 64 + o] = hv;
            sh[nl][o] = hv;
        }
        __syncthreads();
        #pragma unroll
        for (int q = 0; q < 8; q++) {
            int nl = sl + 4 * q;
            float p = 0.f;
            #pragma unroll
            for (int c = 0; c < 8; c++) {
                float4 hv = *(const float4*)&sh[nl][jb + c * 4];
                const float* wrow = &sW1[oo * 65 + jb + c * 4];
                p += wrow[0]*hv.x + wrow[1]*hv.y + wrow[2]*hv.z + wrow[3]*hv.w;
            }
            sp[nl][o] = p;
        }
        __syncthreads();
        if (o < 32) {
            #pragma unroll
            for (int q = 0; q < 8; q++) {
                int nl = sl + 4 * q, node = nbase + nl;
                if (node < N_NODES) g_y1[node * 32 + o] = sp[nl][o] + sp[nl][o + 32];
            }
        }
        __syncthreads();
    }
}

// ---------------- node kernel 1: h2 -> y2 AND z2 (no g_h2 round-trip) -------
__global__ void __launch_bounds__(256, 2)
k_node1(const float* __restrict__ b1,   // [32]
        const float* __restrict__ Wt1,  // [32,64]
        const float* __restrict__ Wr2,  // [16,32]
        const float* __restrict__ Wt2)  // [16,32]
{
    int t = threadIdx.x;
    int o = t & 31, sl = t >> 5;
    float wt1[64];
    #pragma unroll
    for (int j = 0; j < 64; j++) wt1[j] = Wt1[o * 64 + j];
    float bias = b1[o];
    int oo = o & 15, jb = (o < 16) ? 0 : 16;

    __shared__ float sW2y[16 * 33];
    __shared__ float sW2z[16 * 33];
    __shared__ float sh1[32][64];
    __shared__ float sh2[32][32];
    for (int i = t; i < 16 * 32; i += 256) {
        sW2y[(i >> 5) * 33 + (i & 31)] = Wr2[i];
        sW2z[(i >> 5) * 33 + (i & 31)] = Wt2[i];
    }
    __syncthreads();

    for (int nbase = blockIdx.x * 32; nbase < N_NODES; nbase += gridDim.x * 32) {
        for (int i = t; i < 512; i += 256) {
            int n2 = i >> 4, r = i & 15;
            int nn = nbase + n2;
            if (nn < N_NODES)
                *(float4*)&sh1[n2][r * 4] = *(const float4*)&g_h1[nn * 64 + r * 4];
        }
        __syncthreads();
        float hq[4];
        #pragma unroll
        for (int q = 0; q < 4; q++) {
            int nl = sl + 8 * q, node = nbase + nl;
            float h = bias;
            if (node < N_NODES) h += g_agg1[node * 32 + o];
            #pragma unroll
            for (int c = 0; c < 16; c++) {
                float4 hv = *(const float4*)&sh1[nl][c * 4];
                h += wt1[4*c+0]*hv.x + wt1[4*c+1]*hv.y + wt1[4*c+2]*hv.z + wt1[4*c+3]*hv.w;
            }
            hq[q] = tanhf(h);
        }
        #pragma unroll
        for (int q = 0; q < 4; q++) sh2[sl + 8 * q][o] = hq[q];
        __syncwarp();
        #pragma unroll
        for (int q = 0; q < 4; q++) {
            int nl = sl + 8 * q, node = nbase + nl;
            float py = 0.f, pz = 0.f;
            #pragma unroll
            for (int c = 0; c < 4; c++) {
                float4 hv = *(const float4*)&sh2[nl][jb + c * 4];
                const float* wy = &sW2y[oo * 33 + jb + c * 4];
                const float* wz = &sW2z[oo * 33 + jb + c * 4];
                py += wy[0]*hv.x + wy[1]*hv.y + wy[2]*hv.z + wy[3]*hv.w;
                pz += wz[0]*hv.x + wz[1]*hv.y + wz[2]*hv.z + wz[3]*hv.w;
            }
            float oy = __shfl_down_sync(0xffffffffu, py, 16);
            float oz = __shfl_down_sync(0xffffffffu, pz, 16);
            if (node < N_NODES && o < 16) {
                g_y2[node * 16 + o] = py + oy;
                g_z2[node * 16 + o] = pz + oz;
            }
        }
        __syncthreads();
    }
}

// ---------------- final: out = tanh(pool / max(cnt,1)) ----------------------
__global__ void k_final(float* __restrict__ out) {
    int t = blockIdx.x * blockDim.x + threadIdx.x;
    if (t < N_GRAPHS * 16) {
        int g = t >> 4;
        out[t] = tanhf(g_pool[t] / fmaxf(g_cnt[g], 1.0f));
    }
}

extern "C" void kernel_launch(void* const* d_in, const int* in_sizes, int n_in,
                              void* d_out, int out_size) {
    const float* x         = (const float*)d_in[0];
    const int*   ei_raw    = (const int*)d_in[1];
    const int*   batch_raw = (const int*)d_in[2];
    const float* Wr0 = (const float*)d_in[3];
    const float* b0  = (const float*)d_in[4];
    const float* Wt0 = (const float*)d_in[5];
    const float* Wr1 = (const float*)d_in[6];
    const float* b1  = (const float*)d_in[7];
    const float* Wt1 = (const float*)d_in[8];
    const float* Wr2 = (const float*)d_in[9];
    const float* b2  = (const float*)d_in[10];
    const float* Wt2 = (const float*)d_in[11];
    float* out = (float*)d_out;

    k_detect<<<1, 1>>>(ei_raw, batch_raw);
    k_prep<<<2048, 256>>>(x, ei_raw);
    // CSR build (once, reused by all 3 layers)
    k_hist<<<2048, 256>>>();
    k_scan1<<<391, 256>>>();
    k_scan2<<<1, 512>>>();
    k_scan3<<<391, 256>>>();
    k_place<<<2048, 256>>>();
    // layer 0
    k_agg0<<<(N_NODES * 32 + 255) / 256, 256>>>();
    k_node0<<<592, 256>>>(Wr0, b0, Wt0, Wr1);
    // layer 1
    k_agg1<<<(N_NODES * 32 + 255) / 256, 256>>>();
    k_node1<<<592, 256>>>(b1, Wt1, Wr2, Wt2);
    // layer 2 (gather fused with node update + pooling)
    k_agg2_pool<<<(N_NODES * 16 + 255) / 256, 256>>>(batch_raw, b2);
    k_final<<<16, 256>>>(out);
}